// round 1
// baseline (speedup 1.0000x reference)
#include <cuda_runtime.h>

// Problem constants (fixed by the dataset)
#define NPOP   44
#define BATCH  400000
#define B4     (BATCH / 4)      // 100000 float4 per population
#define BPP    20               // blocks per population
#define CHUNK4 (B4 / BPP)       // 5000 float4 per block
#define TPB    256

typedef unsigned long long u64;

// ---- packed f32x2 helpers (Blackwell FFMA2 path) ----

__device__ __forceinline__ u64 pk2(float a) {
    u64 r;
    asm("mov.b64 %0, {%1, %1};" : "=l"(r) : "f"(a));
    return r;
}

__device__ __forceinline__ u64 pk(float a, float b) {
    u64 r;
    asm("mov.b64 %0, {%1, %2};" : "=l"(r) : "f"(a), "f"(b));
    return r;
}

__device__ __forceinline__ void upk(u64 v, float& a, float& b) {
    asm("mov.b64 {%0, %1}, %2;" : "=f"(a), "=f"(b) : "l"(v));
}

__device__ __forceinline__ u64 fma2(u64 a, u64 b, u64 c) {
    u64 d;
    asm("fma.rn.f32x2 %0, %1, %2, %3;" : "=l"(d) : "l"(a), "l"(b), "l"(c));
    return d;
}

// relu on both packed lanes: 2x FMNMX (alu pipe, dual-issues with FFMA2)
__device__ __forceinline__ u64 relu2(u64 v) {
    u64 r;
    asm("{\n\t"
        ".reg .f32 lo, hi;\n\t"
        "mov.b64 {lo, hi}, %1;\n\t"
        "max.f32 lo, lo, 0f00000000;\n\t"
        "max.f32 hi, hi, 0f00000000;\n\t"
        "mov.b64 %0, {lo, hi};\n\t"
        "}" : "=l"(r) : "l"(v));
    return r;
}

// Evaluate the 1->4->8->4->1 MLP on two packed samples.
__device__ __forceinline__ u64 eval_pair(
    u64 xx,
    const u64* __restrict__ w1, const u64* __restrict__ a1,
    const u64* __restrict__ w2, const u64* __restrict__ a2,
    const u64* __restrict__ w3, const u64* __restrict__ a3,
    const u64* __restrict__ w4, u64 a4)
{
    u64 h[4];
#pragma unroll
    for (int i = 0; i < 4; i++)
        h[i] = relu2(fma2(w1[i], xx, a1[i]));

    u64 g[8];
#pragma unroll
    for (int j = 0; j < 8; j++) {
        u64 acc = a2[j];
#pragma unroll
        for (int k = 0; k < 4; k++)
            acc = fma2(w2[j * 4 + k], h[k], acc);
        g[j] = relu2(acc);
    }

    u64 r[4];
#pragma unroll
    for (int i = 0; i < 4; i++) {
        u64 acc = a3[i];
#pragma unroll
        for (int k = 0; k < 8; k++)
            acc = fma2(w3[i * 8 + k], g[k], acc);
        r[i] = relu2(acc);
    }

    u64 acc = a4;
#pragma unroll
    for (int k = 0; k < 4; k++)
        acc = fma2(w4[k], r[k], acc);
    return acc;
}

__global__ void __launch_bounds__(TPB, 1) de_nn_kernel(
    const float* __restrict__ X,
    const float* __restrict__ L1, const float* __restrict__ L2,
    const float* __restrict__ L3, const float* __restrict__ L4,
    const float* __restrict__ B1, const float* __restrict__ B2,
    const float* __restrict__ B3, const float* __restrict__ Bb4,
    float* __restrict__ out)
{
    const int pop = blockIdx.y;
    const int blk = blockIdx.x;

    // --- load weights for this population, duplicated into both f32x2 lanes ---
    u64 w1[4], a1[4], w2[32], a2[8], w3[32], a3[4], w4[4], a4;
    {
        const float* l1 = L1 + pop * 4;
        const float* l2 = L2 + pop * 32;   // (8,4) row-major
        const float* l3 = L3 + pop * 32;   // (4,8) row-major
        const float* l4 = L4 + pop * 4;
        const float* b1 = B1 + pop * 4;
        const float* b2 = B2 + pop * 8;
        const float* b3 = B3 + pop * 4;

#pragma unroll
        for (int i = 0; i < 4; i++)  w1[i] = pk2(__ldg(l1 + i));
#pragma unroll
        for (int i = 0; i < 4; i++)  a1[i] = pk2(__ldg(b1 + i));
#pragma unroll
        for (int i = 0; i < 32; i++) w2[i] = pk2(__ldg(l2 + i));
#pragma unroll
        for (int i = 0; i < 8; i++)  a2[i] = pk2(__ldg(b2 + i));
#pragma unroll
        for (int i = 0; i < 32; i++) w3[i] = pk2(__ldg(l3 + i));
#pragma unroll
        for (int i = 0; i < 4; i++)  a3[i] = pk2(__ldg(b3 + i));
#pragma unroll
        for (int i = 0; i < 4; i++)  w4[i] = pk2(__ldg(l4 + i));
        a4 = pk2(__ldg(Bb4 + pop));
    }

    const float4* __restrict__ X4 =
        reinterpret_cast<const float4*>(X) + (size_t)pop * B4 + (size_t)blk * CHUNK4;
    float4* __restrict__ O4 =
        reinterpret_cast<float4*>(out) + (size_t)pop * B4 + (size_t)blk * CHUNK4;

    int t = threadIdx.x;
    if (t >= CHUNK4) return;

    // register double-buffer so the next DRAM load overlaps this iteration's math
    float4 x = __ldcs(X4 + t);
    while (true) {
        const int tn = t + TPB;
        float4 xn;
        const bool more = (tn < CHUNK4);
        if (more) xn = __ldcs(X4 + tn);

        u64 p0 = pk(x.x, x.y);
        u64 p1 = pk(x.z, x.w);
        u64 o01 = eval_pair(p0, w1, a1, w2, a2, w3, a3, w4, a4);
        u64 o23 = eval_pair(p1, w1, a1, w2, a2, w3, a3, w4, a4);

        float4 o;
        upk(o01, o.x, o.y);
        upk(o23, o.z, o.w);
        __stcs(O4 + t, o);

        if (!more) break;
        x = xn;
        t = tn;
    }
}

extern "C" void kernel_launch(void* const* d_in, const int* in_sizes, int n_in,
                              void* d_out, int out_size)
{
    const float* X  = (const float*)d_in[0];
    const float* L1 = (const float*)d_in[1];
    const float* L2 = (const float*)d_in[2];
    const float* L3 = (const float*)d_in[3];
    const float* L4 = (const float*)d_in[4];
    const float* B1 = (const float*)d_in[5];
    const float* B2 = (const float*)d_in[6];
    const float* B3 = (const float*)d_in[7];
    const float* B4v = (const float*)d_in[8];
    float* out = (float*)d_out;

    dim3 grid(BPP, NPOP);
    de_nn_kernel<<<grid, TPB>>>(X, L1, L2, L3, L4, B1, B2, B3, B4v, out);
}

// round 2
// speedup vs baseline: 1.5977x; 1.5977x over previous
#include <cuda_runtime.h>
#include <math.h>

#define NPOP   44
#define BATCH  400000
#define B4     (BATCH / 4)
#define BPP    20
#define CHUNK4 (B4 / BPP)
#define TPB    256

#define MAXB   232          // >= 224 theoretical max breaks (+ margin)
#define G      2048         // lookup grid slots
#define XLO    (-6.5f)
#define XHI    (6.5f)
#define MARGIN 1e-4f

// --------- scratch (device globals: allowed; no allocs) ---------
__device__ float  g_brk[NPOP][MAXB];
__device__ int    g_nb[NPOP];
__device__ float2 g_pieces[NPOP][MAXB];
__device__ float2 g_grid[NPOP][G];

struct Wt {
    float w1[4], b1[4];
    float w2[8][4], b2[8];
    float w3[4][8], b3[4];
    float w4[4], b4;
};

__device__ __forceinline__ int lbound(const float* a, int n, float x) {
    int lo = 0, hi = n;
    while (lo < hi) { int m = (lo + hi) >> 1; if (a[m] < x) lo = m + 1; else hi = m; }
    return lo;
}

__device__ __forceinline__ float seg_mid(const float* brk, int nb, int s) {
    if (nb == 0) return 0.f;
    if (s == 0)  return brk[0] - 1.f;
    if (s == nb) return brk[nb - 1] + 1.f;
    return 0.5f * (brk[s - 1] + brk[s]);
}

// rank-sort smem array a[0..n) using temp t; all threads must call
__device__ void sort_smem(float* a, float* t, int n, int tid) {
    float v = 0.f; int r = 0;
    if (tid < n) {
        v = a[tid];
        for (int k = 0; k < n; k++) {
            float u = a[k];
            r += (u < v) || (u == v && k < tid);
        }
    }
    __syncthreads();
    if (tid < n) t[r] = v;
    __syncthreads();
    if (tid < n) a[tid] = t[tid];
    __syncthreads();
}

// ---------------- precompute: PWL collapse per population ----------------
__global__ void __launch_bounds__(256) precompute_kernel(
    const float* __restrict__ L1, const float* __restrict__ L2,
    const float* __restrict__ L3, const float* __restrict__ L4,
    const float* __restrict__ B1, const float* __restrict__ B2,
    const float* __restrict__ B3, const float* __restrict__ B4v)
{
    __shared__ Wt w;
    __shared__ float  brk[MAXB];
    __shared__ float  tmp[MAXB];
    __shared__ float2 pieces_s[MAXB];
    __shared__ int nb_sh, cnt;

    const int pop = blockIdx.x;
    const int tid = threadIdx.x;

    if (tid < 4)  { w.w1[tid] = L1[pop*4+tid]; w.b1[tid] = B1[pop*4+tid];
                    w.w4[tid] = L4[pop*4+tid]; w.b3[tid] = B3[pop*4+tid]; }
    if (tid < 32) { ((float*)w.w2)[tid] = L2[pop*32+tid];
                    ((float*)w.w3)[tid] = L3[pop*32+tid]; }
    if (tid < 8)  w.b2[tid] = B2[pop*8+tid];
    if (tid == 0) { w.b4 = B4v[pop]; nb_sh = 0; cnt = 0; }
    __syncthreads();

    // ---- stage A: layer-1 breakpoints (<=4), serial on thread 0 ----
    if (tid == 0) {
        float c[4]; int n = 0;
        for (int i = 0; i < 4; i++)
            if (w.w1[i] != 0.0f) { float x0 = -w.b1[i] / w.w1[i]; if (isfinite(x0)) c[n++] = x0; }
        for (int i = 1; i < n; i++) { float v = c[i]; int j = i-1;
            while (j >= 0 && c[j] > v) { c[j+1] = c[j]; j--; } c[j+1] = v; }
        for (int i = 0; i < n; i++) brk[i] = c[i];
        nb_sh = n;
    }
    __syncthreads();
    int nb = nb_sh;

    // ---- stage B: layer-2 preact crossings, one task per (segment, unit) ----
    {
        int tasks = (nb + 1) * 8;
        if (tid < tasks) {
            int seg = tid >> 3, j = tid & 7;
            float xm = seg_mid(brk, nb, seg);
            float s = 0.f, v = w.b2[j];
            for (int k = 0; k < 4; k++) {
                float p = fmaf(w.w1[k], xm, w.b1[k]);
                if (p > 0.f) { s += w.w2[j][k] * w.w1[k]; v += w.w2[j][k] * p; }
            }
            if (s != 0.f) {
                float x0 = xm - v / s;
                float lo = (seg == 0)  ? -3.4e38f : brk[seg-1];
                float hi = (seg == nb) ?  3.4e38f : brk[seg];
                if (isfinite(x0) && x0 > lo && x0 < hi) {
                    int i = atomicAdd(&cnt, 1);
                    tmp[i] = x0;
                }
            }
        }
        __syncthreads();
        if (tid < cnt) brk[nb + tid] = tmp[tid];
        __syncthreads();
        if (tid == 0) { nb_sh += cnt; cnt = 0; }
        __syncthreads();
        nb = nb_sh;
        sort_smem(brk, tmp, nb, tid);
    }

    // ---- stage C: layer-3 preact crossings, one task per (segment, unit) ----
    {
        int tasks = (nb + 1) * 4;
        if (tid < tasks) {
            int seg = tid >> 2, i = tid & 3;
            float xm = seg_mid(brk, nb, seg);
            float hs[4], hv[4];
            for (int k = 0; k < 4; k++) {
                float p = fmaf(w.w1[k], xm, w.b1[k]);
                bool m = p > 0.f;
                hs[k] = m ? w.w1[k] : 0.f;
                hv[k] = m ? p : 0.f;
            }
            float s = 0.f, v = w.b3[i];
            for (int j = 0; j < 8; j++) {
                float us = 0.f, uv = w.b2[j];
                for (int k = 0; k < 4; k++) { us += w.w2[j][k]*hs[k]; uv += w.w2[j][k]*hv[k]; }
                if (uv > 0.f) { s += w.w3[i][j]*us; v += w.w3[i][j]*uv; }
            }
            if (s != 0.f) {
                float x0 = xm - v / s;
                float lo = (seg == 0)  ? -3.4e38f : brk[seg-1];
                float hi = (seg == nb) ?  3.4e38f : brk[seg];
                if (isfinite(x0) && x0 > lo && x0 < hi) {
                    int i2 = atomicAdd(&cnt, 1);
                    tmp[i2] = x0;
                }
            }
        }
        __syncthreads();
        if (tid < cnt) brk[nb + tid] = tmp[tid];
        __syncthreads();
        if (tid == 0) { nb_sh += cnt; cnt = 0; }
        __syncthreads();
        nb = nb_sh;
        sort_smem(brk, tmp, nb, tid);
    }

    // ---- pieces: one task per final segment ----
    if (tid <= nb) {
        int seg = tid;
        float xm = seg_mid(brk, nb, seg);
        float hs[4], hv[4];
        for (int k = 0; k < 4; k++) {
            float p = fmaf(w.w1[k], xm, w.b1[k]);
            bool m = p > 0.f;
            hs[k] = m ? w.w1[k] : 0.f;
            hv[k] = m ? p : 0.f;
        }
        float gs[8], gv[8];
        for (int j = 0; j < 8; j++) {
            float us = 0.f, uv = w.b2[j];
            for (int k = 0; k < 4; k++) { us += w.w2[j][k]*hs[k]; uv += w.w2[j][k]*hv[k]; }
            bool m = uv > 0.f;
            gs[j] = m ? us : 0.f;
            gv[j] = m ? uv : 0.f;
        }
        float rs[4], rv[4];
        for (int i = 0; i < 4; i++) {
            float vs = 0.f, vv = w.b3[i];
            for (int j = 0; j < 8; j++) { vs += w.w3[i][j]*gs[j]; vv += w.w3[i][j]*gv[j]; }
            bool m = vv > 0.f;
            rs[i] = m ? vs : 0.f;
            rv[i] = m ? vv : 0.f;
        }
        float os = 0.f, ov = w.b4;
        for (int i = 0; i < 4; i++) { os += w.w4[i]*rs[i]; ov += w.w4[i]*rv[i]; }
        float2 pc = make_float2(os, ov - os * xm);
        pieces_s[seg] = pc;
        g_pieces[pop][seg] = pc;
    }
    if (tid < nb) g_brk[pop][tid] = brk[tid];
    if (tid == 0) g_nb[pop] = nb;
    __syncthreads();

    // ---- grid fill: pure slots get (slope, intercept), impure get NaN flag ----
    const float wslot = (XHI - XLO) / (float)G;
    for (int s = tid; s < G; s += blockDim.x) {
        float slo = (s == 0)     ? -3.4e38f : XLO + s * wslot;
        float shi = (s == G - 1) ?  3.4e38f : XLO + (s + 1) * wslot;
        int plo = lbound(brk, nb, slo - MARGIN);
        int phi = lbound(brk, nb, shi + MARGIN);
        float2 out;
        if (plo == phi) out = pieces_s[plo];
        else            out = make_float2(__int_as_float(0x7FC00000), 0.f);  // NaN flag
        g_grid[pop][s] = out;
    }
}

// ---------------- eval: table lookup + 1 FMA per sample ----------------
__device__ __forceinline__ float eval1(float x, const float2* __restrict__ grid,
                                       const float2* __restrict__ pieces,
                                       const float* __restrict__ brk, int nb)
{
    const float INVW = (float)G / (XHI - XLO);
    int slot = (int)((x - XLO) * INVW);
    slot = min(max(slot, 0), G - 1);
    float2 c = grid[slot];
    if (__isnanf(c.x)) {                       // rare: break inside slot or tail
        int p = lbound(brk, nb, x);
        c = pieces[p];
    }
    return fmaf(c.x, x, c.y);
}

__global__ void __launch_bounds__(TPB) eval_kernel(const float* __restrict__ X,
                                                   float* __restrict__ out)
{
    __shared__ float2 grid_s[G];
    __shared__ float2 pieces_s[MAXB];
    __shared__ float  brk_s[MAXB];
    __shared__ int    nb_s;

    const int pop = blockIdx.y;
    const int blk = blockIdx.x;

    for (int i = threadIdx.x; i < G; i += TPB) grid_s[i] = g_grid[pop][i];
    for (int i = threadIdx.x; i < MAXB; i += TPB) {
        pieces_s[i] = g_pieces[pop][i];
        brk_s[i]    = g_brk[pop][i];
    }
    if (threadIdx.x == 0) nb_s = g_nb[pop];
    __syncthreads();
    const int nb = nb_s;

    const float4* __restrict__ X4 =
        reinterpret_cast<const float4*>(X) + (size_t)pop * B4 + (size_t)blk * CHUNK4;
    float4* __restrict__ O4 =
        reinterpret_cast<float4*>(out) + (size_t)pop * B4 + (size_t)blk * CHUNK4;

    for (int t = threadIdx.x; t < CHUNK4; t += TPB) {
        float4 x = __ldcs(X4 + t);
        float4 o;
        o.x = eval1(x.x, grid_s, pieces_s, brk_s, nb);
        o.y = eval1(x.y, grid_s, pieces_s, brk_s, nb);
        o.z = eval1(x.z, grid_s, pieces_s, brk_s, nb);
        o.w = eval1(x.w, grid_s, pieces_s, brk_s, nb);
        __stcs(O4 + t, o);
    }
}

extern "C" void kernel_launch(void* const* d_in, const int* in_sizes, int n_in,
                              void* d_out, int out_size)
{
    const float* X  = (const float*)d_in[0];
    const float* L1 = (const float*)d_in[1];
    const float* L2 = (const float*)d_in[2];
    const float* L3 = (const float*)d_in[3];
    const float* L4 = (const float*)d_in[4];
    const float* B1 = (const float*)d_in[5];
    const float* B2 = (const float*)d_in[6];
    const float* B3 = (const float*)d_in[7];
    const float* B4v = (const float*)d_in[8];
    float* out = (float*)d_out;

    precompute_kernel<<<NPOP, 256>>>(L1, L2, L3, L4, B1, B2, B3, B4v);
    dim3 grid(BPP, NPOP);
    eval_kernel<<<grid, TPB>>>(X, out);
}